// round 9
// baseline (speedup 1.0000x reference)
#include <cuda_runtime.h>
#include <cuda_bf16.h>

// db4 level-1 DWT low-pass reconstruction. Shuffle halos, no shared memory,
// front-batched loads (MLP=4), vectorized edge patches, streaming stores.
// Forced 8 CTAs/SM (launch_bounds minBlocks=8 -> 32-reg target) to raise
// time-averaged in-flight DRAM bytes: kernel is latency-bound (DRAM 73%,
// issue 48%, L1 54% -- nothing saturated at occ 61%).
// x: [8192 rows, 4096] fp32. out = low (N floats) then high (N floats).
//
//   ca[K]     = sum_{m=0..7} h[m] * X(2K+1-m)     (X = symmetric-ext x)
//   low[2K]   = h1*ca[K] + h3*ca[K+1] + h5*ca[K+2] + h7*ca[K+3]
//   low[2K+1] = h0*ca[K] + h2*ca[K+1] + h4*ca[K+2] + h6*ca[K+3]
//   high      = x - low

#define ROW_L    4096
#define NTHREADS 256
#define NF4      (ROW_L / 4)     // 1024 float4 per row

__global__ void __launch_bounds__(NTHREADS, 8)
dwt_db4_kernel(const float* __restrict__ x,
               float* __restrict__ low_out,
               float* __restrict__ high_out)
{
    const float h0 = -0.010597401784997278f;
    const float h1 =  0.032883011666982945f;
    const float h2 =  0.030841381835986965f;
    const float h3 = -0.18703481171888114f;
    const float h4 = -0.02798376941698385f;
    const float h5 =  0.6308807679295904f;
    const float h6 =  0.7148465705525415f;
    const float h7 =  0.23037781330885523f;

    const int t = threadIdx.x;
    const int l = t & 31;
    const size_t row = blockIdx.x;
    const float4* __restrict__ xr4 = (const float4*)(x + row * (size_t)ROW_L);
    float4* __restrict__ low4  = (float4*)(low_out  + row * (size_t)ROW_L);
    float4* __restrict__ high4 = (float4*)(high_out + row * (size_t)ROW_L);

    // Front-batched main loads: MLP = 4
    float4 vv[4];
    #pragma unroll
    for (int g = 0; g < 4; ++g)
        vv[g] = xr4[g * NTHREADS + t];

    #pragma unroll
    for (int g = 0; g < 4; ++g) {
        const int F = g * NTHREADS + t;          // float4 index in row
        const float4 v = vv[g];

        // window w[i] = X(4F - 6 + i), i = 0..15
        float w0, w1, w2, w3, w4, w5;
        float w6 = v.x, w7 = v.y, w8 = v.z, w9 = v.w;
        float w10, w11, w12, w13, w14, w15;

        // halos via shuffle (full-warp convergent)
        w2  = __shfl_up_sync(0xffffffffu, v.x, 1);
        w3  = __shfl_up_sync(0xffffffffu, v.y, 1);
        w4  = __shfl_up_sync(0xffffffffu, v.z, 1);
        w5  = __shfl_up_sync(0xffffffffu, v.w, 1);
        w0  = __shfl_up_sync(0xffffffffu, v.z, 2);
        w1  = __shfl_up_sync(0xffffffffu, v.w, 2);
        w10 = __shfl_down_sync(0xffffffffu, v.x, 1);
        w11 = __shfl_down_sync(0xffffffffu, v.y, 1);
        w12 = __shfl_down_sync(0xffffffffu, v.z, 1);
        w13 = __shfl_down_sync(0xffffffffu, v.w, 1);
        w14 = __shfl_down_sync(0xffffffffu, v.x, 2);
        w15 = __shfl_down_sync(0xffffffffu, v.y, 2);

        // warp-edge patches: vectorized predicated loads (L2-hot), with
        // explicit swizzle for the (rare) row-end reflected cases.
        if (l == 0) {
            // need x[4F-6 .. 4F-1]
            const bool refl = (F == 0);
            const float4 A = xr4[refl ? 1 : F - 2];
            const float4 B = xr4[refl ? 0 : F - 1];
            if (refl) { w0 = A.y; w1 = A.x; w2 = B.w; w3 = B.z; w4 = B.y; w5 = B.x; }
            else      { w0 = A.z; w1 = A.w; w2 = B.x; w3 = B.y; w4 = B.z; w5 = B.w; }
        } else if (l == 1) {
            // need x[4F-6], x[4F-5]
            const bool refl = (F == 1);
            const float4 A = xr4[refl ? 0 : F - 2];
            if (refl) { w0 = A.y; w1 = A.x; }
            else      { w0 = A.z; w1 = A.w; }
        }
        if (l == 31) {
            // need x[4F+4 .. 4F+9]
            const bool refl = (F == NF4 - 1);
            const float4 C = xr4[refl ? (NF4 - 1) : F + 1];
            const float4 D = xr4[refl ? (NF4 - 2) : F + 2];
            if (refl) { w10 = C.w; w11 = C.z; w12 = C.y; w13 = C.x; w14 = D.w; w15 = D.z; }
            else      { w10 = C.x; w11 = C.y; w12 = C.z; w13 = C.w; w14 = D.x; w15 = D.y; }
        } else if (l == 30) {
            // need x[4F+8], x[4F+9]
            const bool refl = (F == NF4 - 2);
            const float4 D = xr4[refl ? (NF4 - 1) : F + 2];
            if (refl) { w14 = D.w; w15 = D.z; }
            else      { w14 = D.x; w15 = D.y; }
        }

        // analysis: ca[j] (global coeff index 2F + j), j = 0..4
        // ca_j = sum_m h[m] * w[2j + 7 - m]
        float wv[16] = { w0, w1, w2, w3, w4, w5, w6, w7,
                         w8, w9, w10, w11, w12, w13, w14, w15 };
        float ca[5];
        #pragma unroll
        for (int j = 0; j < 5; ++j) {
            float s;
            s = h0 * wv[2 * j + 7];
            s = fmaf(h1, wv[2 * j + 6], s);
            s = fmaf(h2, wv[2 * j + 5], s);
            s = fmaf(h3, wv[2 * j + 4], s);
            s = fmaf(h4, wv[2 * j + 3], s);
            s = fmaf(h5, wv[2 * j + 2], s);
            s = fmaf(h6, wv[2 * j + 1], s);
            s = fmaf(h7, wv[2 * j + 0], s);
            ca[j] = s;
        }

        // synthesis: pairs p = 0,1 -> outputs x[4F .. 4F+3]
        float le[2], lo[2];
        #pragma unroll
        for (int p = 0; p < 2; ++p) {
            float e;
            e = h1 * ca[p];
            e = fmaf(h3, ca[p + 1], e);
            e = fmaf(h5, ca[p + 2], e);
            e = fmaf(h7, ca[p + 3], e);
            le[p] = e;

            float o;
            o = h0 * ca[p];
            o = fmaf(h2, ca[p + 1], o);
            o = fmaf(h4, ca[p + 2], o);
            o = fmaf(h6, ca[p + 3], o);
            lo[p] = o;
        }

        // streaming stores: outputs are write-once; keep them out of L2's
        // working set so input lines (edge-patch reuse) stay resident.
        __stcs(low4  + F, make_float4(le[0], lo[0], le[1], lo[1]));
        __stcs(high4 + F, make_float4(w6 - le[0], w7 - lo[0],
                                      w8 - le[1], w9 - lo[1]));
    }
}

extern "C" void kernel_launch(void* const* d_in, const int* in_sizes, int n_in,
                              void* d_out, int out_size)
{
    const float* x = (const float*)d_in[0];
    const int n = in_sizes[0];            // 16*512*4096
    float* low  = (float*)d_out;          // outputs concatenated: (low, high)
    float* high = low + (size_t)n;
    const int rows = n / ROW_L;           // 8192
    dwt_db4_kernel<<<rows, NTHREADS>>>(x, low, high);
}

// round 10
// speedup vs baseline: 1.0044x; 1.0044x over previous
#include <cuda_runtime.h>
#include <cuda_bf16.h>

// db4 level-1 DWT low-pass reconstruction. 8 floats per thread (2 adjacent
// float4), distance-1 shuffle halos only, no shared memory, front-batched
// loads (MLP=4), streaming stores.
// x: [8192 rows, 4096] fp32. out = low (N floats) then high (N floats).
//
//   ca[K]     = sum_{m=0..7} h[m] * X(2K+1-m)     (X = symmetric-ext x)
//   low[2K]   = h1*ca[K] + h3*ca[K+1] + h5*ca[K+2] + h7*ca[K+3]
//   low[2K+1] = h0*ca[K] + h2*ca[K+1] + h4*ca[K+2] + h6*ca[K+3]
//   high      = x - low
//
// Thread t, group g in {0,1}: owns float8 E = 256*g + t -> outputs
// x[8E .. 8E+7]. Window w[0..19] = X(8E-6 .. 8E+13):
//   w6..w13  = own two float4 (xr4[2E], xr4[2E+1])
//   w0..w5   = lane t-1 floats 2..7  (6 x shfl_up 1)
//   w14..w19 = lane t+1 floats 0..5  (6 x shfl_down 1)
// Lanes 0/31 patch from global (L2-hot); row ends use symmetric reflection.

#define ROW_L    4096
#define NTHREADS 256
#define NF8      (ROW_L / 8)     // 512 float8 per row
#define NF4      (ROW_L / 4)

__global__ void __launch_bounds__(NTHREADS)
dwt_db4_kernel(const float* __restrict__ x,
               float* __restrict__ low_out,
               float* __restrict__ high_out)
{
    const float h0 = -0.010597401784997278f;
    const float h1 =  0.032883011666982945f;
    const float h2 =  0.030841381835986965f;
    const float h3 = -0.18703481171888114f;
    const float h4 = -0.02798376941698385f;
    const float h5 =  0.6308807679295904f;
    const float h6 =  0.7148465705525415f;
    const float h7 =  0.23037781330885523f;

    const int t = threadIdx.x;
    const int l = t & 31;
    const size_t row = blockIdx.x;
    const float4* __restrict__ xr4 = (const float4*)(x + row * (size_t)ROW_L);
    float4* __restrict__ low4  = (float4*)(low_out  + row * (size_t)ROW_L);
    float4* __restrict__ high4 = (float4*)(high_out + row * (size_t)ROW_L);

    // Front-batched main loads: 4 x LDG.128 (MLP = 4)
    float4 va[2], vb[2];
    #pragma unroll
    for (int g = 0; g < 2; ++g) {
        const int E = g * NTHREADS + t;
        va[g] = xr4[2 * E];
        vb[g] = xr4[2 * E + 1];
    }

    #pragma unroll
    for (int g = 0; g < 2; ++g) {
        const int E = g * NTHREADS + t;      // float8 index in row, 0..511
        const float4 v0 = va[g];             // x[8E   .. 8E+3]
        const float4 v1 = vb[g];             // x[8E+4 .. 8E+7]

        // window w[i] = X(8E - 6 + i), i = 0..19
        float w0, w1, w2, w3, w4, w5;
        const float w6 = v0.x, w7 = v0.y, w8 = v0.z, w9 = v0.w;
        const float w10 = v1.x, w11 = v1.y, w12 = v1.z, w13 = v1.w;
        float w14, w15, w16, w17, w18, w19;

        // halos via distance-1 shuffle (full-warp convergent)
        w0  = __shfl_up_sync(0xffffffffu, v0.z, 1);
        w1  = __shfl_up_sync(0xffffffffu, v0.w, 1);
        w2  = __shfl_up_sync(0xffffffffu, v1.x, 1);
        w3  = __shfl_up_sync(0xffffffffu, v1.y, 1);
        w4  = __shfl_up_sync(0xffffffffu, v1.z, 1);
        w5  = __shfl_up_sync(0xffffffffu, v1.w, 1);
        w14 = __shfl_down_sync(0xffffffffu, v0.x, 1);
        w15 = __shfl_down_sync(0xffffffffu, v0.y, 1);
        w16 = __shfl_down_sync(0xffffffffu, v0.z, 1);
        w17 = __shfl_down_sync(0xffffffffu, v0.w, 1);
        w18 = __shfl_down_sync(0xffffffffu, v1.x, 1);
        w19 = __shfl_down_sync(0xffffffffu, v1.y, 1);

        // warp-edge patches (vectorized, L2-hot); symmetric reflect at row ends
        if (l == 0) {
            // need x[8E-6 .. 8E-1]
            const bool refl = (E == 0);
            const float4 A = xr4[refl ? 1 : 2 * E - 2];
            const float4 B = xr4[refl ? 0 : 2 * E - 1];
            if (refl) { w0 = A.y; w1 = A.x; w2 = B.w; w3 = B.z; w4 = B.y; w5 = B.x; }
            else      { w0 = A.z; w1 = A.w; w2 = B.x; w3 = B.y; w4 = B.z; w5 = B.w; }
        }
        if (l == 31) {
            // need x[8E+8 .. 8E+13]
            const bool refl = (E == NF8 - 1);
            const float4 C = xr4[refl ? (NF4 - 1) : 2 * E + 2];
            const float4 D = xr4[refl ? (NF4 - 2) : 2 * E + 3];
            if (refl) { w14 = C.w; w15 = C.z; w16 = C.y; w17 = C.x; w18 = D.w; w19 = D.z; }
            else      { w14 = C.x; w15 = C.y; w16 = C.z; w17 = C.w; w18 = D.x; w19 = D.y; }
        }

        // analysis: ca[j] (global coeff index 4E + j), j = 0..6
        // ca_j = sum_m h[m] * w[2j + 7 - m]
        const float wv[20] = { w0, w1, w2, w3, w4, w5, w6, w7, w8, w9,
                               w10, w11, w12, w13, w14, w15, w16, w17, w18, w19 };
        float ca[7];
        #pragma unroll
        for (int j = 0; j < 7; ++j) {
            float s;
            s = h0 * wv[2 * j + 7];
            s = fmaf(h1, wv[2 * j + 6], s);
            s = fmaf(h2, wv[2 * j + 5], s);
            s = fmaf(h3, wv[2 * j + 4], s);
            s = fmaf(h4, wv[2 * j + 3], s);
            s = fmaf(h5, wv[2 * j + 2], s);
            s = fmaf(h6, wv[2 * j + 1], s);
            s = fmaf(h7, wv[2 * j + 0], s);
            ca[j] = s;
        }

        // synthesis: pairs p = 0..3 -> outputs x[8E .. 8E+7]
        float le[4], lo[4];
        #pragma unroll
        for (int p = 0; p < 4; ++p) {
            float e;
            e = h1 * ca[p];
            e = fmaf(h3, ca[p + 1], e);
            e = fmaf(h5, ca[p + 2], e);
            e = fmaf(h7, ca[p + 3], e);
            le[p] = e;

            float o;
            o = h0 * ca[p];
            o = fmaf(h2, ca[p + 1], o);
            o = fmaf(h4, ca[p + 2], o);
            o = fmaf(h6, ca[p + 3], o);
            lo[p] = o;
        }

        // streaming stores: write-once outputs, keep out of L2 working set
        __stcs(low4 + 2 * E,     make_float4(le[0], lo[0], le[1], lo[1]));
        __stcs(low4 + 2 * E + 1, make_float4(le[2], lo[2], le[3], lo[3]));
        __stcs(high4 + 2 * E,     make_float4(w6 - le[0], w7 - lo[0],
                                              w8 - le[1], w9 - lo[1]));
        __stcs(high4 + 2 * E + 1, make_float4(w10 - le[2], w11 - lo[2],
                                              w12 - le[3], w13 - lo[3]));
    }
}

extern "C" void kernel_launch(void* const* d_in, const int* in_sizes, int n_in,
                              void* d_out, int out_size)
{
    const float* x = (const float*)d_in[0];
    const int n = in_sizes[0];            // 16*512*4096
    float* low  = (float*)d_out;          // outputs concatenated: (low, high)
    float* high = low + (size_t)n;
    const int rows = n / ROW_L;           // 8192
    dwt_db4_kernel<<<rows, NTHREADS>>>(x, low, high);
}

// round 11
// speedup vs baseline: 1.0255x; 1.0210x over previous
#include <cuda_runtime.h>
#include <cuda_bf16.h>

// db4 level-1 DWT low-pass reconstruction. Shuffle halos, no shared memory,
// front-batched loads (MLP=4), vectorized edge patches, streaming stores.
// Half-row CTAs (128 threads, grid = 2*rows) for finer wave granularity.
// x: [8192 rows, 4096] fp32. out = low (N floats) then high (N floats).
//
//   ca[K]     = sum_{m=0..7} h[m] * X(2K+1-m)     (X = symmetric-ext x)
//   low[2K]   = h1*ca[K] + h3*ca[K+1] + h5*ca[K+2] + h7*ca[K+3]
//   low[2K+1] = h0*ca[K] + h2*ca[K+1] + h4*ca[K+2] + h6*ca[K+3]
//   high      = x - low

#define ROW_L    4096
#define NTHREADS 128
#define NF4      (ROW_L / 4)     // 1024 float4 per row
#define F4_PER_CTA 512           // half row
#define NGROUPS  (F4_PER_CTA / NTHREADS)   // 4

__global__ void __launch_bounds__(NTHREADS)
dwt_db4_kernel(const float* __restrict__ x,
               float* __restrict__ low_out,
               float* __restrict__ high_out)
{
    const float h0 = -0.010597401784997278f;
    const float h1 =  0.032883011666982945f;
    const float h2 =  0.030841381835986965f;
    const float h3 = -0.18703481171888114f;
    const float h4 = -0.02798376941698385f;
    const float h5 =  0.6308807679295904f;
    const float h6 =  0.7148465705525415f;
    const float h7 =  0.23037781330885523f;

    const int t = threadIdx.x;
    const int l = t & 31;
    const size_t row  = blockIdx.x >> 1;
    const int    half = blockIdx.x & 1;
    const int    base = half * F4_PER_CTA;     // float4 offset of this CTA

    const float4* __restrict__ xr4 = (const float4*)(x + row * (size_t)ROW_L);
    float4* __restrict__ low4  = (float4*)(low_out  + row * (size_t)ROW_L);
    float4* __restrict__ high4 = (float4*)(high_out + row * (size_t)ROW_L);

    // Front-batched main loads: MLP = 4
    float4 vv[NGROUPS];
    #pragma unroll
    for (int g = 0; g < NGROUPS; ++g)
        vv[g] = xr4[base + g * NTHREADS + t];

    #pragma unroll
    for (int g = 0; g < NGROUPS; ++g) {
        const int F = base + g * NTHREADS + t;   // float4 index in row
        const float4 v = vv[g];

        // window w[i] = X(4F - 6 + i), i = 0..15
        float w0, w1, w2, w3, w4, w5;
        float w6 = v.x, w7 = v.y, w8 = v.z, w9 = v.w;
        float w10, w11, w12, w13, w14, w15;

        // halos via shuffle (full-warp convergent)
        w2  = __shfl_up_sync(0xffffffffu, v.x, 1);
        w3  = __shfl_up_sync(0xffffffffu, v.y, 1);
        w4  = __shfl_up_sync(0xffffffffu, v.z, 1);
        w5  = __shfl_up_sync(0xffffffffu, v.w, 1);
        w0  = __shfl_up_sync(0xffffffffu, v.z, 2);
        w1  = __shfl_up_sync(0xffffffffu, v.w, 2);
        w10 = __shfl_down_sync(0xffffffffu, v.x, 1);
        w11 = __shfl_down_sync(0xffffffffu, v.y, 1);
        w12 = __shfl_down_sync(0xffffffffu, v.z, 1);
        w13 = __shfl_down_sync(0xffffffffu, v.w, 1);
        w14 = __shfl_down_sync(0xffffffffu, v.x, 2);
        w15 = __shfl_down_sync(0xffffffffu, v.y, 2);

        // warp-edge patches: vectorized predicated loads (L2-hot), with
        // explicit swizzle for the (rare) row-end reflected cases.
        if (l == 0) {
            // need x[4F-6 .. 4F-1]
            const bool refl = (F == 0);
            const float4 A = xr4[refl ? 1 : F - 2];
            const float4 B = xr4[refl ? 0 : F - 1];
            if (refl) { w0 = A.y; w1 = A.x; w2 = B.w; w3 = B.z; w4 = B.y; w5 = B.x; }
            else      { w0 = A.z; w1 = A.w; w2 = B.x; w3 = B.y; w4 = B.z; w5 = B.w; }
        } else if (l == 1) {
            // need x[4F-6], x[4F-5]
            const bool refl = (F == 1);
            const float4 A = xr4[refl ? 0 : F - 2];
            if (refl) { w0 = A.y; w1 = A.x; }
            else      { w0 = A.z; w1 = A.w; }
        }
        if (l == 31) {
            // need x[4F+4 .. 4F+9]
            const bool refl = (F == NF4 - 1);
            const float4 C = xr4[refl ? (NF4 - 1) : F + 1];
            const float4 D = xr4[refl ? (NF4 - 2) : F + 2];
            if (refl) { w10 = C.w; w11 = C.z; w12 = C.y; w13 = C.x; w14 = D.w; w15 = D.z; }
            else      { w10 = C.x; w11 = C.y; w12 = C.z; w13 = C.w; w14 = D.x; w15 = D.y; }
        } else if (l == 30) {
            // need x[4F+8], x[4F+9]
            const bool refl = (F == NF4 - 2);
            const float4 D = xr4[refl ? (NF4 - 1) : F + 2];
            if (refl) { w14 = D.w; w15 = D.z; }
            else      { w14 = D.x; w15 = D.y; }
        }

        // analysis: ca[j] (global coeff index 2F + j), j = 0..4
        // ca_j = sum_m h[m] * w[2j + 7 - m]
        float wv[16] = { w0, w1, w2, w3, w4, w5, w6, w7,
                         w8, w9, w10, w11, w12, w13, w14, w15 };
        float ca[5];
        #pragma unroll
        for (int j = 0; j < 5; ++j) {
            float s;
            s = h0 * wv[2 * j + 7];
            s = fmaf(h1, wv[2 * j + 6], s);
            s = fmaf(h2, wv[2 * j + 5], s);
            s = fmaf(h3, wv[2 * j + 4], s);
            s = fmaf(h4, wv[2 * j + 3], s);
            s = fmaf(h5, wv[2 * j + 2], s);
            s = fmaf(h6, wv[2 * j + 1], s);
            s = fmaf(h7, wv[2 * j + 0], s);
            ca[j] = s;
        }

        // synthesis: pairs p = 0,1 -> outputs x[4F .. 4F+3]
        float le[2], lo[2];
        #pragma unroll
        for (int p = 0; p < 2; ++p) {
            float e;
            e = h1 * ca[p];
            e = fmaf(h3, ca[p + 1], e);
            e = fmaf(h5, ca[p + 2], e);
            e = fmaf(h7, ca[p + 3], e);
            le[p] = e;

            float o;
            o = h0 * ca[p];
            o = fmaf(h2, ca[p + 1], o);
            o = fmaf(h4, ca[p + 2], o);
            o = fmaf(h6, ca[p + 3], o);
            lo[p] = o;
        }

        // streaming stores: write-once outputs, keep out of L2 working set
        __stcs(low4  + F, make_float4(le[0], lo[0], le[1], lo[1]));
        __stcs(high4 + F, make_float4(w6 - le[0], w7 - lo[0],
                                      w8 - le[1], w9 - lo[1]));
    }
}

extern "C" void kernel_launch(void* const* d_in, const int* in_sizes, int n_in,
                              void* d_out, int out_size)
{
    const float* x = (const float*)d_in[0];
    const int n = in_sizes[0];            // 16*512*4096
    float* low  = (float*)d_out;          // outputs concatenated: (low, high)
    float* high = low + (size_t)n;
    const int rows = n / ROW_L;           // 8192
    dwt_db4_kernel<<<rows * 2, NTHREADS>>>(x, low, high);
}

// round 12
// speedup vs baseline: 1.0327x; 1.0071x over previous
#include <cuda_runtime.h>
#include <cuda_bf16.h>

// db4 level-1 DWT low-pass reconstruction. 8 contiguous floats per thread via
// Blackwell 256-bit vector ld/st (ld.global.nc.v8.f32 / st.global.v8.f32),
// distance-1 shuffle halos, no shared memory, front-batched loads.
// x: [8192 rows, 4096] fp32. out = low (N floats) then high (N floats).
//
//   ca[K]     = sum_{m=0..7} h[m] * X(2K+1-m)     (X = symmetric-ext x)
//   low[2K]   = h1*ca[K] + h3*ca[K+1] + h5*ca[K+2] + h7*ca[K+3]
//   low[2K+1] = h0*ca[K] + h2*ca[K+1] + h4*ca[K+2] + h6*ca[K+3]
//   high      = x - low
//
// Thread t (256/CTA), group g in {0,1}: owns float8 E = 256*g + t ->
// outputs x[8E .. 8E+7]. Window w[0..19] = X(8E-6 .. 8E+13):
//   w6..w13  = own float8 (one LDG.256)
//   w0..w5   = lane t-1 floats 2..7  (6 x shfl_up 1)
//   w14..w19 = lane t+1 floats 0..5  (6 x shfl_down 1)
// Lanes 0/31 patch from global (L2-hot); row ends symmetric-reflect.

#define ROW_L    4096
#define NTHREADS 256
#define NF8      (ROW_L / 8)     // 512 float8 per row
#define NF4      (ROW_L / 4)

struct F8 { float v[8]; };

__device__ __forceinline__ F8 ldg256(const float* p) {
    F8 r;
    asm("ld.global.nc.v8.f32 {%0,%1,%2,%3,%4,%5,%6,%7}, [%8];"
        : "=f"(r.v[0]), "=f"(r.v[1]), "=f"(r.v[2]), "=f"(r.v[3]),
          "=f"(r.v[4]), "=f"(r.v[5]), "=f"(r.v[6]), "=f"(r.v[7])
        : "l"(p));
    return r;
}

__device__ __forceinline__ void stg256(float* p,
                                       float a0, float a1, float a2, float a3,
                                       float a4, float a5, float a6, float a7) {
    asm volatile("st.global.v8.f32 [%0], {%1,%2,%3,%4,%5,%6,%7,%8};"
        :: "l"(p), "f"(a0), "f"(a1), "f"(a2), "f"(a3),
           "f"(a4), "f"(a5), "f"(a6), "f"(a7)
        : "memory");
}

__global__ void __launch_bounds__(NTHREADS)
dwt_db4_kernel(const float* __restrict__ x,
               float* __restrict__ low_out,
               float* __restrict__ high_out)
{
    const float h0 = -0.010597401784997278f;
    const float h1 =  0.032883011666982945f;
    const float h2 =  0.030841381835986965f;
    const float h3 = -0.18703481171888114f;
    const float h4 = -0.02798376941698385f;
    const float h5 =  0.6308807679295904f;
    const float h6 =  0.7148465705525415f;
    const float h7 =  0.23037781330885523f;

    const int t = threadIdx.x;
    const int l = t & 31;
    const size_t row = blockIdx.x;
    const float*  __restrict__ xr  = x + row * (size_t)ROW_L;
    const float4* __restrict__ xr4 = (const float4*)xr;
    float* __restrict__ lowp  = low_out  + row * (size_t)ROW_L;
    float* __restrict__ highp = high_out + row * (size_t)ROW_L;

    // Front-batched main loads: 2 x LDG.256 (64B per thread in flight)
    F8 va[2];
    #pragma unroll
    for (int g = 0; g < 2; ++g)
        va[g] = ldg256(xr + (size_t)(g * NTHREADS + t) * 8);

    #pragma unroll
    for (int g = 0; g < 2; ++g) {
        const int E = g * NTHREADS + t;      // float8 index in row, 0..511
        const F8 v = va[g];

        // window w[i] = X(8E - 6 + i), i = 0..19
        float w0, w1, w2, w3, w4, w5;
        const float w6 = v.v[0], w7 = v.v[1], w8 = v.v[2], w9 = v.v[3];
        const float w10 = v.v[4], w11 = v.v[5], w12 = v.v[6], w13 = v.v[7];
        float w14, w15, w16, w17, w18, w19;

        // halos via distance-1 shuffle (full-warp convergent)
        w0  = __shfl_up_sync(0xffffffffu, v.v[2], 1);
        w1  = __shfl_up_sync(0xffffffffu, v.v[3], 1);
        w2  = __shfl_up_sync(0xffffffffu, v.v[4], 1);
        w3  = __shfl_up_sync(0xffffffffu, v.v[5], 1);
        w4  = __shfl_up_sync(0xffffffffu, v.v[6], 1);
        w5  = __shfl_up_sync(0xffffffffu, v.v[7], 1);
        w14 = __shfl_down_sync(0xffffffffu, v.v[0], 1);
        w15 = __shfl_down_sync(0xffffffffu, v.v[1], 1);
        w16 = __shfl_down_sync(0xffffffffu, v.v[2], 1);
        w17 = __shfl_down_sync(0xffffffffu, v.v[3], 1);
        w18 = __shfl_down_sync(0xffffffffu, v.v[4], 1);
        w19 = __shfl_down_sync(0xffffffffu, v.v[5], 1);

        // warp-edge patches (vectorized, L2-hot); symmetric reflect at row ends
        if (l == 0) {
            // need x[8E-6 .. 8E-1]
            const bool refl = (E == 0);
            const float4 A = xr4[refl ? 1 : 2 * E - 2];
            const float4 B = xr4[refl ? 0 : 2 * E - 1];
            if (refl) { w0 = A.y; w1 = A.x; w2 = B.w; w3 = B.z; w4 = B.y; w5 = B.x; }
            else      { w0 = A.z; w1 = A.w; w2 = B.x; w3 = B.y; w4 = B.z; w5 = B.w; }
        }
        if (l == 31) {
            // need x[8E+8 .. 8E+13]
            const bool refl = (E == NF8 - 1);
            const float4 C = xr4[refl ? (NF4 - 1) : 2 * E + 2];
            const float4 D = xr4[refl ? (NF4 - 2) : 2 * E + 3];
            if (refl) { w14 = C.w; w15 = C.z; w16 = C.y; w17 = C.x; w18 = D.w; w19 = D.z; }
            else      { w14 = C.x; w15 = C.y; w16 = C.z; w17 = C.w; w18 = D.x; w19 = D.y; }
        }

        // analysis: ca[j] (global coeff index 4E + j), j = 0..6
        // ca_j = sum_m h[m] * w[2j + 7 - m]
        const float wv[20] = { w0, w1, w2, w3, w4, w5, w6, w7, w8, w9,
                               w10, w11, w12, w13, w14, w15, w16, w17, w18, w19 };
        float ca[7];
        #pragma unroll
        for (int j = 0; j < 7; ++j) {
            float s;
            s = h0 * wv[2 * j + 7];
            s = fmaf(h1, wv[2 * j + 6], s);
            s = fmaf(h2, wv[2 * j + 5], s);
            s = fmaf(h3, wv[2 * j + 4], s);
            s = fmaf(h4, wv[2 * j + 3], s);
            s = fmaf(h5, wv[2 * j + 2], s);
            s = fmaf(h6, wv[2 * j + 1], s);
            s = fmaf(h7, wv[2 * j + 0], s);
            ca[j] = s;
        }

        // synthesis: pairs p = 0..3 -> outputs x[8E .. 8E+7]
        float le[4], lo[4];
        #pragma unroll
        for (int p = 0; p < 4; ++p) {
            float e;
            e = h1 * ca[p];
            e = fmaf(h3, ca[p + 1], e);
            e = fmaf(h5, ca[p + 2], e);
            e = fmaf(h7, ca[p + 3], e);
            le[p] = e;

            float o;
            o = h0 * ca[p];
            o = fmaf(h2, ca[p + 1], o);
            o = fmaf(h4, ca[p + 2], o);
            o = fmaf(h6, ca[p + 3], o);
            lo[p] = o;
        }

        stg256(lowp + (size_t)E * 8,
               le[0], lo[0], le[1], lo[1], le[2], lo[2], le[3], lo[3]);
        stg256(highp + (size_t)E * 8,
               w6 - le[0], w7 - lo[0], w8 - le[1], w9 - lo[1],
               w10 - le[2], w11 - lo[2], w12 - le[3], w13 - lo[3]);
    }
}

extern "C" void kernel_launch(void* const* d_in, const int* in_sizes, int n_in,
                              void* d_out, int out_size)
{
    const float* x = (const float*)d_in[0];
    const int n = in_sizes[0];            // 16*512*4096
    float* low  = (float*)d_out;          // outputs concatenated: (low, high)
    float* high = low + (size_t)n;
    const int rows = n / ROW_L;           // 8192
    dwt_db4_kernel<<<rows, NTHREADS>>>(x, low, high);
}